// round 4
// baseline (speedup 1.0000x reference)
#include <cuda_runtime.h>
#include <cuda_bf16.h>
#include <cstdint>

// Problem constants
#define N_SAMPLES    65536
#define START_SIZE   4096
#define N_EVENTS     32
#define ROW_F4       (N_SAMPLES / 4)          // 16384 float4 per row
#define SEGS_PER_ROW 8
#define SEG_F4       (ROW_F4 / SEGS_PER_ROW)  // 2048 float4 per segment
#define THREADS      256
#define F4_PER_THR   (SEG_F4 / THREADS)       // 8
#define POS_F4       (START_SIZE / 4)         // 1024 float4 per event

// Order-preserving unsigned key for float compare
__device__ __forceinline__ unsigned ord_key(float v) {
    unsigned u = __float_as_uint(v);
    return (u & 0x80000000u) ? ~u : (u | 0x80000000u);
}

__global__ void __launch_bounds__(THREADS)
fused_shift_kernel(const float4* __restrict__ in,
                   const float4* __restrict__ pos,
                   float4* __restrict__ out)
{
    const int bid = blockIdx.x;
    const int tid = threadIdx.x;
    const int row = bid >> 3;                   // bid / SEGS_PER_ROW
    const int seg = bid & (SEGS_PER_ROW - 1);
    const int e   = row & (N_EVENTS - 1);
    const size_t rbase = (size_t)row * ROW_F4;
    const int j0 = seg * SEG_F4 + tid;
    const float4* src_base = in + rbase + j0;

    // ---- Phase 1: issue all event loads immediately (shift-independent) ---
    float4 vals[F4_PER_THR];
    #pragma unroll
    for (int k = 0; k < F4_PER_THR; k++)
        vals[k] = src_base[k * THREADS];

    // ---- Phase 2: redundant argmax over pos[e] (L2-hot, overlaps loads) ---
    // jnp.argmax tie rule: first index wins.
    // key = (ord(val) << 32) | (~idx)  ->  max() prefers larger val, then
    // smaller index.
    const float4* p4 = pos + (size_t)e * POS_F4;
    unsigned long long best = 0ull;
    #pragma unroll
    for (int kk = 0; kk < POS_F4 / THREADS; kk++) {      // 4 iterations
        const int i4 = tid + kk * THREADS;
        const float4 v = __ldg(&p4[i4]);
        const int b = i4 * 4;
        unsigned long long k0 = ((unsigned long long)ord_key(v.x) << 32) | (0xFFFFFFFFu - (unsigned)(b + 0));
        unsigned long long k1 = ((unsigned long long)ord_key(v.y) << 32) | (0xFFFFFFFFu - (unsigned)(b + 1));
        unsigned long long k2 = ((unsigned long long)ord_key(v.z) << 32) | (0xFFFFFFFFu - (unsigned)(b + 2));
        unsigned long long k3 = ((unsigned long long)ord_key(v.w) << 32) | (0xFFFFFFFFu - (unsigned)(b + 3));
        if (k0 > best) best = k0;
        if (k1 > best) best = k1;
        if (k2 > best) best = k2;
        if (k3 > best) best = k3;
    }
    #pragma unroll
    for (int off = 16; off > 0; off >>= 1) {
        unsigned long long o = __shfl_down_sync(0xFFFFFFFFu, best, off);
        if (o > best) best = o;
    }

    __shared__ unsigned long long s_best[THREADS / 32];  // 8 warps
    __shared__ int s_d4;
    if ((tid & 31) == 0) s_best[tid >> 5] = best;
    __syncthreads();
    if (tid == 0) {
        unsigned long long b = s_best[0];
        #pragma unroll
        for (int w = 1; w < THREADS / 32; w++)
            if (s_best[w] > b) b = s_best[w];
        const int idx = (int)(0xFFFFFFFFu - (unsigned)(b & 0xFFFFFFFFu));
        s_d4 = idx * 4;                       // STEP=16 floats = 4 float4
    }
    __syncthreads();
    const int d4 = s_d4;

    // ---- Phase 3: shifted stores. out[(j+d4) mod ROW_F4] ------------------
    // j+d4 <  ROW_F4 : out[j+d4]          = in[j]
    // j+d4 >= ROW_F4 : out[j+d4-ROW_F4]   = 0   (bijective head-zeroing)
    float4* dst_base = out + rbase;
    #pragma unroll
    for (int k = 0; k < F4_PER_THR; k++) {
        const int jp = j0 + k * THREADS + d4;
        if (jp < ROW_F4) {
            dst_base[jp] = vals[k];
        } else {
            dst_base[jp - ROW_F4] = make_float4(0.f, 0.f, 0.f, 0.f);
        }
    }
}

extern "C" void kernel_launch(void* const* d_in, const int* in_sizes, int n_in,
                              void* d_out, int out_size) {
    const float* events = (const float*)d_in[0];   // (B, 32, 65536) f32
    const float* pos    = (const float*)d_in[1];   // (1, 32, 4096)  f32

    const int batch = in_sizes[0] / (N_EVENTS * N_SAMPLES);   // 8
    const int rows  = batch * N_EVENTS;                       // 256
    const int grid  = rows * SEGS_PER_ROW;                    // 2048

    fused_shift_kernel<<<grid, THREADS>>>((const float4*)events,
                                          (const float4*)pos,
                                          (float4*)d_out);
}

// round 7
// speedup vs baseline: 1.1782x; 1.1782x over previous
#include <cuda_runtime.h>
#include <cuda_bf16.h>
#include <cstdint>

// Problem constants
#define N_SAMPLES    65536
#define START_SIZE   4096
#define N_EVENTS     32
#define ROW_F4       (N_SAMPLES / 4)          // 16384 float4 per row
#define SEGS_PER_ROW 8
#define SEG_F4       (ROW_F4 / SEGS_PER_ROW)  // 2048 float4 per segment
#define THREADS      256
#define F4_PER_THR   (SEG_F4 / THREADS)       // 8
#define POS_F4       (START_SIZE / 4)         // 1024 float4 per event
#define POS_ITERS    (POS_F4 / THREADS)       // 4
#define NWARPS       (THREADS / 32)           // 8

// Order-preserving unsigned key for float compare (no NaNs in inputs)
__device__ __forceinline__ unsigned ord_key(float v) {
    unsigned u = __float_as_uint(v);
    return (u & 0x80000000u) ? ~u : (u | 0x80000000u);
}
__device__ __forceinline__ float key_to_float(unsigned k) {
    unsigned u = (k & 0x80000000u) ? (k ^ 0x80000000u) : ~k;
    return __uint_as_float(u);
}

__device__ __forceinline__ unsigned warp_max_u32(unsigned v) {
    #pragma unroll
    for (int off = 16; off > 0; off >>= 1)
        v = max(v, __shfl_down_sync(0xFFFFFFFFu, v, off));
    return v;
}
__device__ __forceinline__ unsigned warp_min_u32(unsigned v) {
    #pragma unroll
    for (int off = 16; off > 0; off >>= 1)
        v = min(v, __shfl_down_sync(0xFFFFFFFFu, v, off));
    return v;
}

__global__ void __launch_bounds__(THREADS)
fused_shift_kernel(const float4* __restrict__ in,
                   const float4* __restrict__ pos,
                   float4* __restrict__ out)
{
    const int bid = blockIdx.x;
    const int tid = threadIdx.x;
    const int row = bid >> 3;                   // bid / SEGS_PER_ROW
    const int seg = bid & (SEGS_PER_ROW - 1);
    const int e   = row & (N_EVENTS - 1);
    const size_t rbase = (size_t)row * ROW_F4;
    const int j0 = seg * SEG_F4 + tid;
    const float4* src_base = in + rbase + j0;

    // ---- Phase 1: issue all event loads immediately (shift-independent) ---
    float4 vals[F4_PER_THR];
    #pragma unroll
    for (int k = 0; k < F4_PER_THR; k++)
        vals[k] = src_base[k * THREADS];

    // ---- Phase 2a: max value over pos[e] (FMNMX chain, overlaps loads) ----
    const float4* p4 = pos + (size_t)e * POS_F4;
    float mx = __int_as_float(0xff800000);      // -inf
    #pragma unroll
    for (int kk = 0; kk < POS_ITERS; kk++) {
        const float4 v = p4[tid + kk * THREADS];
        mx = fmaxf(mx, fmaxf(fmaxf(v.x, v.y), fmaxf(v.z, v.w)));
    }
    const unsigned wkey = warp_max_u32(ord_key(mx));

    __shared__ unsigned s_wkey[NWARPS];
    __shared__ unsigned s_widx[NWARPS];
    __shared__ int s_d4;
    if ((tid & 31) == 0) s_wkey[tid >> 5] = wkey;
    __syncthreads();

    unsigned bkey = s_wkey[0];
    #pragma unroll
    for (int w = 1; w < NWARPS; w++) bkey = max(bkey, s_wkey[w]);
    const float bmax = key_to_float(bkey);

    // ---- Phase 2b: first index equal to max (reload is L1-hot) -----------
    // Process descending so the final surviving write is the SMALLEST index
    // (jnp.argmax first-match tie rule).
    unsigned li = 0xFFFFFFFFu;
    #pragma unroll
    for (int kk = POS_ITERS - 1; kk >= 0; kk--) {
        const int i4 = tid + kk * THREADS;
        const float4 v = p4[i4];
        const unsigned b = (unsigned)(i4 * 4);
        li = (v.w == bmax) ? b + 3u : li;
        li = (v.z == bmax) ? b + 2u : li;
        li = (v.y == bmax) ? b + 1u : li;
        li = (v.x == bmax) ? b + 0u : li;
    }
    const unsigned wmin = warp_min_u32(li);
    if ((tid & 31) == 0) s_widx[tid >> 5] = wmin;
    __syncthreads();

    if (tid == 0) {
        unsigned idx = 0xFFFFFFFFu;
        #pragma unroll
        for (int w = 0; w < NWARPS; w++) idx = min(idx, s_widx[w]);
        s_d4 = (int)idx * 4;                  // STEP=16 floats = 4 float4
    }
    __syncthreads();
    const int d4 = s_d4;

    // ---- Phase 3: shifted streaming stores. out[(j+d4) mod ROW_F4] -------
    // j+d4 <  ROW_F4 : out[j+d4]        = in[j]
    // j+d4 >= ROW_F4 : out[j+d4-ROW_F4] = 0   (bijective head-zeroing)
    float4* dst_base = out + rbase;
    const float4 zero = make_float4(0.f, 0.f, 0.f, 0.f);
    #pragma unroll
    for (int k = 0; k < F4_PER_THR; k++) {
        const int jp = j0 + k * THREADS + d4;
        if (jp < ROW_F4) {
            __stcs(dst_base + jp, vals[k]);
        } else {
            __stcs(dst_base + jp - ROW_F4, zero);
        }
    }
}

extern "C" void kernel_launch(void* const* d_in, const int* in_sizes, int n_in,
                              void* d_out, int out_size) {
    const float* events = (const float*)d_in[0];   // (B, 32, 65536) f32
    const float* pos    = (const float*)d_in[1];   // (1, 32, 4096)  f32

    const int batch = in_sizes[0] / (N_EVENTS * N_SAMPLES);   // 8
    const int rows  = batch * N_EVENTS;                       // 256
    const int grid  = rows * SEGS_PER_ROW;                    // 2048

    fused_shift_kernel<<<grid, THREADS>>>((const float4*)events,
                                          (const float4*)pos,
                                          (float4*)d_out);
}